// round 8
// baseline (speedup 1.0000x reference)
#include <cuda_runtime.h>
#include <cstdint>

#define NNODES_MAX 40000
#define NEDGES_MAX 640000
#define D 128
#define D4 32

// ---------------- device scratch (no allocation allowed) ----------------
__device__ __align__(16) float g_agg[NNODES_MAX * D];
__device__ __align__(16) float g_h1 [NNODES_MAX * D];
__device__ __align__(16) float g_sum[D];
__device__ __align__(16) float g_sq [D];
__device__ int g_cnt[NNODES_MAX];
__device__ int g_off[NNODES_MAX + 1];
__device__ int g_cur[NNODES_MAX];
__device__ int g_srcs[NEDGES_MAX];

__device__ __forceinline__ uint32_t f2tf32(float x) {
    uint32_t r; asm("cvt.rna.tf32.f32 %0, %1;" : "=r"(r) : "f"(x)); return r;
}

// ---------------- CSR build: zero -> hist -> scan -> reorder ----------------
__global__ void k_zero(int N) {
    int i = blockIdx.x * blockDim.x + threadIdx.x;
    if (i < N) g_cnt[i] = 0;
    if (i < D) { g_sum[i] = 0.f; g_sq[i] = 0.f; }
}

__global__ void k_hist(const int* __restrict__ dst, int E, int N) {
    int i = blockIdx.x * blockDim.x + threadIdx.x;
    if (i >= E) return;
    int d = dst[i];
    if ((unsigned)d < (unsigned)N) atomicAdd(&g_cnt[d], 1);
}

__global__ void __launch_bounds__(1024) k_scan(int N) {
    __shared__ int part[1024];
    int t = threadIdx.x;
    const int CH = (N + 1023) / 1024;
    int base = t * CH;
    int s = 0;
    for (int i = 0; i < CH; i++) { int idx = base + i; if (idx < N) s += g_cnt[idx]; }
    part[t] = s;
    __syncthreads();
    for (int off = 1; off < 1024; off <<= 1) {
        int v = (t >= off) ? part[t - off] : 0;
        __syncthreads();
        part[t] += v;
        __syncthreads();
    }
    int run = (t == 0) ? 0 : part[t - 1];
    for (int i = 0; i < CH; i++) {
        int idx = base + i;
        if (idx < N) { g_off[idx] = run; g_cur[idx] = run; run += g_cnt[idx]; }
    }
    if (t == 1023) g_off[N] = run;
}

__global__ void k_reorder(const int* __restrict__ src, const int* __restrict__ dst,
                          int E, int N) {
    int i = blockIdx.x * blockDim.x + threadIdx.x;
    if (i >= E) return;
    int d = dst[i];
    int s = src[i];
    if ((unsigned)d >= (unsigned)N || (unsigned)s >= (unsigned)N) return;
    int p = atomicAdd(&g_cur[d], 1);
    g_srcs[p] = s;
}

// ---------------- per-node register aggregation (absorbs init_agg) ----------------
__global__ void __launch_bounds__(256) k_aggregate(const float* __restrict__ x,
                                                   const float* __restrict__ eps, int N) {
    int warp = (blockIdx.x * blockDim.x + threadIdx.x) >> 5;
    int lane = threadIdx.x & 31;
    if (warp >= N) return;
    float sEps = 1.0f + eps[0];
    float4 acc = ((const float4*)(x + (size_t)warp * D))[lane];
    acc.x *= sEps; acc.y *= sEps; acc.z *= sEps; acc.w *= sEps;
    int b = g_off[warp], e = g_off[warp + 1];
    for (int i = b; i < e; ++i) {
        int s = g_srcs[i];
        float4 v = ((const float4*)(x + (size_t)s * D))[lane];
        acc.x += fmaxf(v.x, 0.f); acc.y += fmaxf(v.y, 0.f);
        acc.z += fmaxf(v.z, 0.f); acc.w += fmaxf(v.w, 0.f);
    }
    ((float4*)(g_agg + (size_t)warp * D))[lane] = acc;
}

// ---------------- tf32 mma.sync GEMM, W-resident + reg-prefetch pipeline ----------------
// MODE 0: A = g_agg -> C = g_h1, fused BN column stats.
// MODE 1: A = BNReLU(g_h1) -> C = out, BN scale/shift computed in-block from g_sum/g_sq.
__device__ __forceinline__ void mma_tf32(float* c, const uint32_t* a, const uint32_t* b) {
    asm volatile("mma.sync.aligned.m16n8k8.row.col.f32.tf32.tf32.f32 "
                 "{%0,%1,%2,%3}, {%4,%5,%6,%7}, {%8,%9}, {%0,%1,%2,%3};"
                 : "+f"(c[0]), "+f"(c[1]), "+f"(c[2]), "+f"(c[3])
                 : "r"(a[0]), "r"(a[1]), "r"(a[2]), "r"(a[3]), "r"(b[0]), "r"(b[1]));
}

template <int MODE>
__global__ void __launch_bounds__(256, 2) k_gemm_mma(const float* __restrict__ Wm,
                                                     const float* __restrict__ bias,
                                                     const float* __restrict__ gamma,
                                                     const float* __restrict__ beta,
                                                     float* __restrict__ outp, int nrows) {
    __shared__ float sW[128][132];
    __shared__ float sA[2][128][36];
    __shared__ float sScale[128], sShift[128];

    const float* __restrict__ A = (MODE == 0) ? g_agg : g_h1;
    float* __restrict__ Cp      = (MODE == 0) ? g_h1  : outp;

    int tid  = threadIdx.x;
    int wid  = tid >> 5, lane = tid & 31;
    int g    = lane >> 2, t4 = lane & 3;
    int wm   = (wid >> 2) * 64;
    int wn   = (wid & 3) * 32;
    int rowbase = blockIdx.x * 128;

    if (MODE == 1 && tid < D) {
        float invN = 1.0f / (float)nrows;
        float mu   = g_sum[tid] * invN;
        float var  = g_sq[tid] * invN - mu * mu;
        float sc   = rsqrtf(var + 1e-5f) * gamma[tid];
        sScale[tid] = sc;
        sShift[tid] = beta[tid] - mu * sc;
    }

    // ---- load full W into smem (tf32-rounded) ----
#pragma unroll
    for (int it = 0; it < 16; ++it) {
        int i  = tid + it * 256;
        int r  = i >> 5;
        int c4 = i & 31;
        float4 v = ((const float4*)Wm)[(size_t)r * D4 + c4];
        float* p = &sW[r][c4 * 4];
        p[0] = __uint_as_float(f2tf32(v.x));
        p[1] = __uint_as_float(f2tf32(v.y));
        p[2] = __uint_as_float(f2tf32(v.z));
        p[3] = __uint_as_float(f2tf32(v.w));
    }

    float acc[4][4][4];
#pragma unroll
    for (int mi = 0; mi < 4; mi++)
#pragma unroll
        for (int nj = 0; nj < 4; nj++)
#pragma unroll
            for (int q = 0; q < 4; q++) acc[mi][nj][q] = 0.f;

    int rS  = tid >> 3;
    int c4S = tid & 7;

    // ---- prefetch A chunk 0 ----
    float4 pf[4];
#pragma unroll
    for (int it = 0; it < 4; ++it) {
        int grow = rowbase + rS + it * 32;
        pf[it] = make_float4(0.f, 0.f, 0.f, 0.f);
        if (grow < nrows) pf[it] = ((const float4*)A)[(size_t)grow * D4 + c4S];
    }
    __syncthreads();   // W (and MODE-1 scale/shift) visible

    for (int kc = 0; kc < 4; ++kc) {
        int buf = kc & 1;
#pragma unroll
        for (int it = 0; it < 4; ++it) {
            float4 v = pf[it];
            if (MODE == 1) {
                int k0 = kc * 32 + c4S * 4;
                float4 sc = *(const float4*)&sScale[k0];
                float4 sh = *(const float4*)&sShift[k0];
                v.x = fmaxf(fmaf(v.x, sc.x, sh.x), 0.f);
                v.y = fmaxf(fmaf(v.y, sc.y, sh.y), 0.f);
                v.z = fmaxf(fmaf(v.z, sc.z, sh.z), 0.f);
                v.w = fmaxf(fmaf(v.w, sc.w, sh.w), 0.f);
            }
            float* p = &sA[buf][rS + it * 32][c4S * 4];
            p[0] = __uint_as_float(f2tf32(v.x));
            p[1] = __uint_as_float(f2tf32(v.y));
            p[2] = __uint_as_float(f2tf32(v.z));
            p[3] = __uint_as_float(f2tf32(v.w));
        }
        __syncthreads();

        if (kc < 3) {
#pragma unroll
            for (int it = 0; it < 4; ++it) {
                int grow = rowbase + rS + it * 32;
                pf[it] = make_float4(0.f, 0.f, 0.f, 0.f);
                if (grow < nrows) pf[it] = ((const float4*)A)[(size_t)grow * D4 + (kc + 1) * 8 + c4S];
            }
        }

#pragma unroll
        for (int ks = 0; ks < 4; ++ks) {
            int ka = ks * 8;
            int kw = kc * 32 + ka;
            uint32_t af[4][4];
#pragma unroll
            for (int mi = 0; mi < 4; mi++) {
                int r = wm + mi * 16 + g;
                af[mi][0] = __float_as_uint(sA[buf][r    ][ka + t4    ]);
                af[mi][1] = __float_as_uint(sA[buf][r + 8][ka + t4    ]);
                af[mi][2] = __float_as_uint(sA[buf][r    ][ka + t4 + 4]);
                af[mi][3] = __float_as_uint(sA[buf][r + 8][ka + t4 + 4]);
            }
            uint32_t bf[4][2];
#pragma unroll
            for (int nj = 0; nj < 4; nj++) {
                int c = wn + nj * 8 + g;
                bf[nj][0] = __float_as_uint(sW[c][kw + t4    ]);
                bf[nj][1] = __float_as_uint(sW[c][kw + t4 + 4]);
            }
#pragma unroll
            for (int mi = 0; mi < 4; mi++)
#pragma unroll
                for (int nj = 0; nj < 4; nj++)
                    mma_tf32(acc[mi][nj], af[mi], bf[nj]);
        }
    }

    // ---- epilogue ----
    float bj0[4], bj1[4];
#pragma unroll
    for (int nj = 0; nj < 4; nj++) {
        int c = wn + nj * 8 + 2 * t4;
        bj0[nj] = bias[c];
        bj1[nj] = bias[c + 1];
    }

    float s0[4], s1[4], q0[4], q1[4];
#pragma unroll
    for (int nj = 0; nj < 4; nj++) { s0[nj] = s1[nj] = q0[nj] = q1[nj] = 0.f; }

#pragma unroll
    for (int mi = 0; mi < 4; mi++) {
        int r0 = rowbase + wm + mi * 16 + g;
        int r1 = r0 + 8;
#pragma unroll
        for (int nj = 0; nj < 4; nj++) {
            int c = wn + nj * 8 + 2 * t4;
            float v00 = acc[mi][nj][0] + bj0[nj];
            float v01 = acc[mi][nj][1] + bj1[nj];
            float v10 = acc[mi][nj][2] + bj0[nj];
            float v11 = acc[mi][nj][3] + bj1[nj];
            if (r0 < nrows) {
                *(float2*)&Cp[(size_t)r0 * D + c] = make_float2(v00, v01);
                if (MODE == 0) {
                    s0[nj] += v00; s1[nj] += v01;
                    q0[nj] = fmaf(v00, v00, q0[nj]); q1[nj] = fmaf(v01, v01, q1[nj]);
                }
            }
            if (r1 < nrows) {
                *(float2*)&Cp[(size_t)r1 * D + c] = make_float2(v10, v11);
                if (MODE == 0) {
                    s0[nj] += v10; s1[nj] += v11;
                    q0[nj] = fmaf(v10, v10, q0[nj]); q1[nj] = fmaf(v11, v11, q1[nj]);
                }
            }
        }
    }

    if (MODE == 0) {
#pragma unroll
        for (int nj = 0; nj < 4; nj++) {
#pragma unroll
            for (int m = 4; m <= 16; m <<= 1) {
                s0[nj] += __shfl_xor_sync(0xFFFFFFFFu, s0[nj], m);
                s1[nj] += __shfl_xor_sync(0xFFFFFFFFu, s1[nj], m);
                q0[nj] += __shfl_xor_sync(0xFFFFFFFFu, q0[nj], m);
                q1[nj] += __shfl_xor_sync(0xFFFFFFFFu, q1[nj], m);
            }
        }
        if (lane < 4) {
#pragma unroll
            for (int nj = 0; nj < 4; nj++) {
                int c = wn + nj * 8 + 2 * t4;
                atomicAdd(&g_sum[c],     s0[nj]);
                atomicAdd(&g_sum[c + 1], s1[nj]);
                atomicAdd(&g_sq [c],     q0[nj]);
                atomicAdd(&g_sq [c + 1], q1[nj]);
            }
        }
    }
}

// ---------------- launch ----------------
extern "C" void kernel_launch(void* const* d_in, const int* in_sizes, int n_in,
                              void* d_out, int out_size) {
    const float* x     = (const float*)d_in[0];
    const int*   src   = (const int*)d_in[1];
    const int*   dst   = (const int*)d_in[2];
    const float* W1    = (const float*)d_in[3];
    const float* b1    = (const float*)d_in[4];
    const float* gamma = (const float*)d_in[5];
    const float* beta  = (const float*)d_in[6];
    const float* W2    = (const float*)d_in[7];
    const float* b2    = (const float*)d_in[8];
    const float* eps   = (const float*)d_in[9];
    float* out = (float*)d_out;

    int N = in_sizes[0] / D;     // 40000
    int E = in_sizes[1];         // 640000

    k_zero<<<(N + 255) / 256, 256>>>(N);
    k_hist<<<(E + 255) / 256, 256>>>(dst, E, N);
    k_scan<<<1, 1024>>>(N);
    k_reorder<<<(E + 255) / 256, 256>>>(src, dst, E, N);
    k_aggregate<<<(N * 32 + 255) / 256, 256>>>(x, eps, N);

    int gb = (N + 127) / 128;
    k_gemm_mma<0><<<gb, 256>>>(W1, b1, nullptr, nullptr, nullptr, N);  // + fused BN stats
    k_gemm_mma<1><<<gb, 256>>>(W2, b2, gamma, beta, out, N);           // BN folded in prologue
}

// round 9
// speedup vs baseline: 1.3058x; 1.3058x over previous
#include <cuda_runtime.h>
#include <cstdint>

#define NNODES_MAX 40000
#define D 128
#define D4 32

// ---------------- device scratch (no allocation allowed) ----------------
__device__ __align__(16) float g_agg[NNODES_MAX * D];
__device__ __align__(16) float g_h1 [NNODES_MAX * D];
__device__ __align__(16) float g_sum[D];
__device__ __align__(16) float g_sq [D];

__device__ __forceinline__ uint32_t f2tf32(float x) {
    uint32_t r; asm("cvt.rna.tf32.f32 %0, %1;" : "=r"(r) : "f"(x)); return r;
}
__device__ __forceinline__ uint32_t smem_u32(const void* p) {
    uint32_t a;
    asm("{ .reg .u64 t; cvta.to.shared.u64 t, %1; cvt.u32.u64 %0, t; }" : "=r"(a) : "l"(p));
    return a;
}

// ---------------- init: residual scale + zero BN stats (fused) ----------------
__global__ void k_init_agg(const float* __restrict__ x, const float* __restrict__ eps, int n4) {
    int i = blockIdx.x * blockDim.x + threadIdx.x;
    if (blockIdx.x == 0 && threadIdx.x < D) { g_sum[threadIdx.x] = 0.f; g_sq[threadIdx.x] = 0.f; }
    if (i >= n4) return;
    float s = 1.0f + eps[0];
    float4 v = ((const float4*)x)[i];
    v.x *= s; v.y *= s; v.z *= s; v.w *= s;
    ((float4*)g_agg)[i] = v;
}

// ---------------- edge scatter: one warp per edge, vector reduction ----------------
__device__ __forceinline__ void red_add_v4(float* addr, float4 v) {
    asm volatile("red.global.add.v4.f32 [%0], {%1, %2, %3, %4};"
                 :: "l"(addr), "f"(v.x), "f"(v.y), "f"(v.z), "f"(v.w) : "memory");
}

__global__ void k_scatter(const float* __restrict__ x,
                          const int* __restrict__ src,
                          const int* __restrict__ dst, int E, int N) {
    int lane = threadIdx.x & 31;
    int warp = (blockIdx.x * blockDim.x + threadIdx.x) >> 5;
    int nwarps = (gridDim.x * blockDim.x) >> 5;
    for (int e = warp; e < E; e += nwarps) {
        int s = src[e];
        int d = dst[e];
        if ((unsigned)s >= (unsigned)N || (unsigned)d >= (unsigned)N) continue;
        float4 v = ((const float4*)(x + (long long)s * D))[lane];
        v.x = fmaxf(v.x, 0.f); v.y = fmaxf(v.y, 0.f);
        v.z = fmaxf(v.z, 0.f); v.w = fmaxf(v.w, 0.f);
        red_add_v4(g_agg + (long long)d * D + (lane << 2), v);
    }
}

// ---------------- tf32 mma.sync GEMM: W-resident smem + cp.async A pipeline ----------------
// C[i,j] = sum_k A[i,k]*W[j,k] + bias[j]
// MODE 0: A = g_agg -> C = g_h1, fused BN column stats into g_sum/g_sq.
// MODE 1: A = BNReLU(g_h1) -> C = out, BN scale/shift computed in prologue from g_sum/g_sq.
__device__ __forceinline__ void mma_tf32(float* c, const uint32_t* a, const uint32_t* b) {
    asm volatile("mma.sync.aligned.m16n8k8.row.col.f32.tf32.tf32.f32 "
                 "{%0,%1,%2,%3}, {%4,%5,%6,%7}, {%8,%9}, {%0,%1,%2,%3};"
                 : "+f"(c[0]), "+f"(c[1]), "+f"(c[2]), "+f"(c[3])
                 : "r"(a[0]), "r"(a[1]), "r"(a[2]), "r"(a[3]), "r"(b[0]), "r"(b[1]));
}

template <int MODE>
__global__ void __launch_bounds__(256, 2) k_gemm_mma(const float* __restrict__ Wm,
                                                     const float* __restrict__ bias,
                                                     const float* __restrict__ gamma,
                                                     const float* __restrict__ beta,
                                                     float* __restrict__ outp, int nrows) {
    __shared__ float sW[128][132];      // full W, tf32-rounded; (4c+t4) mod 32 all-distinct
    __shared__ float sA[2][128][36];    // raw fp32 A chunks (32 k each), cp.async-filled
    __shared__ float sScale[128], sShift[128];

    const float* __restrict__ A = (MODE == 0) ? g_agg : g_h1;
    float* __restrict__ Cp      = (MODE == 0) ? g_h1  : outp;

    int tid  = threadIdx.x;
    int wid  = tid >> 5, lane = tid & 31;
    int g    = lane >> 2, t4 = lane & 3;
    int wm   = (wid >> 2) * 64;
    int wn   = (wid & 3) * 32;
    int rowbase = blockIdx.x * 128;

    if (MODE == 1 && tid < D) {
        float invN = 1.0f / (float)nrows;
        float mu   = g_sum[tid] * invN;
        float var  = g_sq[tid] * invN - mu * mu;
        float sc   = rsqrtf(var + 1e-5f) * gamma[tid];
        sScale[tid] = sc;
        sShift[tid] = beta[tid] - mu * sc;
    }

    // ---- load full W into smem (tf32-rounded) ----
#pragma unroll
    for (int it = 0; it < 16; ++it) {
        int i  = tid + it * 256;
        int r  = i >> 5;
        int c4 = i & 31;
        float4 v = ((const float4*)Wm)[(size_t)r * D4 + c4];
        float* p = &sW[r][c4 * 4];
        p[0] = __uint_as_float(f2tf32(v.x));
        p[1] = __uint_as_float(f2tf32(v.y));
        p[2] = __uint_as_float(f2tf32(v.z));
        p[3] = __uint_as_float(f2tf32(v.w));
    }

    int rS  = tid >> 3;                 // 0..31 row slot
    int c4S = tid & 7;                  // float4 column within chunk

    // cp.async issue for one chunk: 4x 16B per thread, zero-fill out-of-range rows
    auto issue_chunk = [&](int kc, int buf) {
#pragma unroll
        for (int it = 0; it < 4; ++it) {
            int r = rS + it * 32;
            int grow = rowbase + r;
            uint32_t dstA = smem_u32(&sA[buf][r][c4S * 4]);
            const float* srcp = A + (size_t)grow * D + kc * 32 + c4S * 4;
            int valid = (grow < nrows) ? 16 : 0;
            asm volatile("cp.async.cg.shared.global [%0], [%1], 16, %2;"
                         :: "r"(dstA), "l"(srcp), "r"(valid) : "memory");
        }
        asm volatile("cp.async.commit_group;" ::: "memory");
    };

    float acc[4][4][4];
#pragma unroll
    for (int mi = 0; mi < 4; mi++)
#pragma unroll
        for (int nj = 0; nj < 4; nj++)
#pragma unroll
            for (int q = 0; q < 4; q++) acc[mi][nj][q] = 0.f;

    issue_chunk(0, 0);
    __syncthreads();        // W / sScale visible before MMAs; joins warps

    for (int kc = 0; kc < 4; ++kc) {
        int buf = kc & 1;
        if (kc < 3) issue_chunk(kc + 1, buf ^ 1);
        if (kc < 3) asm volatile("cp.async.wait_group 1;" ::: "memory");
        else        asm volatile("cp.async.wait_group 0;" ::: "memory");
        __syncthreads();    // chunk kc visible to all warps

#pragma unroll
        for (int ks = 0; ks < 4; ++ks) {
            int ka = ks * 8;
            int kw = kc * 32 + ka;
            float sc0 = 0.f, sh0 = 0.f, sc1 = 0.f, sh1 = 0.f;
            if (MODE == 1) {
                sc0 = sScale[kw + t4];     sh0 = sShift[kw + t4];
                sc1 = sScale[kw + t4 + 4]; sh1 = sShift[kw + t4 + 4];
            }
            uint32_t af[4][4];
#pragma unroll
            for (int mi = 0; mi < 4; mi++) {
                int r = wm + mi * 16 + g;
                float a0 = sA[buf][r    ][ka + t4    ];
                float a1 = sA[buf][r + 8][ka + t4    ];
                float a2 = sA[buf][r    ][ka + t4 + 4];
                float a3 = sA[buf][r + 8][ka + t4 + 4];
                if (MODE == 1) {
                    a0 = fmaxf(fmaf(a0, sc0, sh0), 0.f);
                    a1 = fmaxf(fmaf(a1, sc0, sh0), 0.f);
                    a2 = fmaxf(fmaf(a2, sc1, sh1), 0.f);
                    a3 = fmaxf(fmaf(a3, sc1, sh1), 0.f);
                }
                af[mi][0] = f2tf32(a0);
                af[mi][1] = f2tf32(a1);
                af[mi][2] = f2tf32(a2);
                af[mi][3] = f2tf32(a3);
            }
            uint32_t bf[4][2];
#pragma unroll
            for (int nj = 0; nj < 4; nj++) {
                int c = wn + nj * 8 + g;
                bf[nj][0] = __float_as_uint(sW[c][kw + t4    ]);
                bf[nj][1] = __float_as_uint(sW[c][kw + t4 + 4]);
            }
#pragma unroll
            for (int mi = 0; mi < 4; mi++)
#pragma unroll
                for (int nj = 0; nj < 4; nj++)
                    mma_tf32(acc[mi][nj], af[mi], bf[nj]);
        }
        __syncthreads();    // MMAs on buf done before next issue overwrites it
    }

    // ---- epilogue: bias add, store, (MODE 0) fused BN column stats ----
    float bj0[4], bj1[4];
#pragma unroll
    for (int nj = 0; nj < 4; nj++) {
        int c = wn + nj * 8 + 2 * t4;
        bj0[nj] = bias[c];
        bj1[nj] = bias[c + 1];
    }

    float s0[4], s1[4], q0[4], q1[4];
#pragma unroll
    for (int nj = 0; nj < 4; nj++) { s0[nj] = s1[nj] = q0[nj] = q1[nj] = 0.f; }

#pragma unroll
    for (int mi = 0; mi < 4; mi++) {
        int r0 = rowbase + wm + mi * 16 + g;
        int r1 = r0 + 8;
#pragma unroll
        for (int nj = 0; nj < 4; nj++) {
            int c = wn + nj * 8 + 2 * t4;
            float v00 = acc[mi][nj][0] + bj0[nj];
            float v01 = acc[mi][nj][1] + bj1[nj];
            float v10 = acc[mi][nj][2] + bj0[nj];
            float v11 = acc[mi][nj][3] + bj1[nj];
            if (r0 < nrows) {
                *(float2*)&Cp[(size_t)r0 * D + c] = make_float2(v00, v01);
                if (MODE == 0) {
                    s0[nj] += v00; s1[nj] += v01;
                    q0[nj] = fmaf(v00, v00, q0[nj]); q1[nj] = fmaf(v01, v01, q1[nj]);
                }
            }
            if (r1 < nrows) {
                *(float2*)&Cp[(size_t)r1 * D + c] = make_float2(v10, v11);
                if (MODE == 0) {
                    s0[nj] += v10; s1[nj] += v11;
                    q0[nj] = fmaf(v10, v10, q0[nj]); q1[nj] = fmaf(v11, v11, q1[nj]);
                }
            }
        }
    }

    if (MODE == 0) {
#pragma unroll
        for (int nj = 0; nj < 4; nj++) {
#pragma unroll
            for (int m = 4; m <= 16; m <<= 1) {
                s0[nj] += __shfl_xor_sync(0xFFFFFFFFu, s0[nj], m);
                s1[nj] += __shfl_xor_sync(0xFFFFFFFFu, s1[nj], m);
                q0[nj] += __shfl_xor_sync(0xFFFFFFFFu, q0[nj], m);
                q1[nj] += __shfl_xor_sync(0xFFFFFFFFu, q1[nj], m);
            }
        }
        if (lane < 4) {
#pragma unroll
            for (int nj = 0; nj < 4; nj++) {
                int c = wn + nj * 8 + 2 * t4;
                atomicAdd(&g_sum[c],     s0[nj]);
                atomicAdd(&g_sum[c + 1], s1[nj]);
                atomicAdd(&g_sq [c],     q0[nj]);
                atomicAdd(&g_sq [c + 1], q1[nj]);
            }
        }
    }
}

// ---------------- launch ----------------
extern "C" void kernel_launch(void* const* d_in, const int* in_sizes, int n_in,
                              void* d_out, int out_size) {
    const float* x     = (const float*)d_in[0];
    const int*   src   = (const int*)d_in[1];
    const int*   dst   = (const int*)d_in[2];
    const float* W1    = (const float*)d_in[3];
    const float* b1    = (const float*)d_in[4];
    const float* gamma = (const float*)d_in[5];
    const float* beta  = (const float*)d_in[6];
    const float* W2    = (const float*)d_in[7];
    const float* b2    = (const float*)d_in[8];
    const float* eps   = (const float*)d_in[9];
    float* out = (float*)d_out;

    int N = in_sizes[0] / D;     // 40000
    int E = in_sizes[1];         // 640000
    int n4 = N * D4;

    k_init_agg<<<(n4 + 255) / 256, 256>>>(x, eps, n4);
    k_scatter<<<2048, 256>>>(x, src, dst, E, N);

    int gb = (N + 127) / 128;
    k_gemm_mma<0><<<gb, 256>>>(W1, b1, nullptr, nullptr, nullptr, N);  // + fused BN stats
    k_gemm_mma<1><<<gb, 256>>>(W2, b2, gamma, beta, out, N);           // BN folded in prologue
}

// round 11
// speedup vs baseline: 1.3261x; 1.0155x over previous
#include <cuda_runtime.h>
#include <cstdint>

#define NNODES_MAX 40000
#define D 128
#define D4 32

// ---------------- device scratch (no allocation allowed) ----------------
__device__ __align__(16) float g_agg[NNODES_MAX * D];
__device__ __align__(16) float g_h1 [NNODES_MAX * D];
__device__ __align__(16) float g_sum[D];
__device__ __align__(16) float g_sq [D];

__device__ __forceinline__ uint32_t f2tf32(float x) {
    uint32_t r; asm("cvt.rna.tf32.f32 %0, %1;" : "=r"(r) : "f"(x)); return r;
}
__device__ __forceinline__ uint32_t smem_u32(const void* p) {
    uint32_t a;
    asm("{ .reg .u64 t; cvta.to.shared.u64 t, %1; cvt.u32.u64 %0, t; }" : "=r"(a) : "l"(p));
    return a;
}

// ---------------- init: residual scale + zero BN stats (fused) ----------------
__global__ void k_init_agg(const float* __restrict__ x, const float* __restrict__ eps, int n4) {
    int i = blockIdx.x * blockDim.x + threadIdx.x;
    if (blockIdx.x == 0 && threadIdx.x < D) { g_sum[threadIdx.x] = 0.f; g_sq[threadIdx.x] = 0.f; }
    if (i >= n4) return;
    float s = 1.0f + eps[0];
    float4 v = ((const float4*)x)[i];
    v.x *= s; v.y *= s; v.z *= s; v.w *= s;
    ((float4*)g_agg)[i] = v;
}

// ---------------- edge scatter: one warp per edge, vector reduction ----------------
__device__ __forceinline__ void red_add_v4(float* addr, float4 v) {
    asm volatile("red.global.add.v4.f32 [%0], {%1, %2, %3, %4};"
                 :: "l"(addr), "f"(v.x), "f"(v.y), "f"(v.z), "f"(v.w) : "memory");
}

__global__ void k_scatter(const float* __restrict__ x,
                          const int* __restrict__ src,
                          const int* __restrict__ dst, int E, int N) {
    int lane = threadIdx.x & 31;
    int warp = (blockIdx.x * blockDim.x + threadIdx.x) >> 5;
    int nwarps = (gridDim.x * blockDim.x) >> 5;
    for (int e = warp; e < E; e += nwarps) {
        int s = src[e];
        int d = dst[e];
        if ((unsigned)s >= (unsigned)N || (unsigned)d >= (unsigned)N) continue;
        float4 v = ((const float4*)(x + (long long)s * D))[lane];
        v.x = fmaxf(v.x, 0.f); v.y = fmaxf(v.y, 0.f);
        v.z = fmaxf(v.z, 0.f); v.w = fmaxf(v.w, 0.f);
        red_add_v4(g_agg + (long long)d * D + (lane << 2), v);
    }
}

// ---------------- tf32 mma.sync GEMM: cp.async-streamed A and W ----------------
// C[i,j] = sum_k A[i,k]*W[j,k] + bias[j]
// MODE 0: A = g_agg -> C = g_h1, fused BN column stats into g_sum/g_sq.
// MODE 1: A = BNReLU(g_h1) -> C = out, BN scale/shift computed in prologue from g_sum/g_sq.
// Pipeline: wait -> barrier -> issue(next) -> MMA.  The barrier orders every warp's
// MMA(kc-1) reads of buf^1 before any warp's cp.async overwrites it (single barrier/iter).
__device__ __forceinline__ void mma_tf32(float* c, const uint32_t* a, const uint32_t* b) {
    asm volatile("mma.sync.aligned.m16n8k8.row.col.f32.tf32.tf32.f32 "
                 "{%0,%1,%2,%3}, {%4,%5,%6,%7}, {%8,%9}, {%0,%1,%2,%3};"
                 : "+f"(c[0]), "+f"(c[1]), "+f"(c[2]), "+f"(c[3])
                 : "r"(a[0]), "r"(a[1]), "r"(a[2]), "r"(a[3]), "r"(b[0]), "r"(b[1]));
}

template <int MODE>
__global__ void __launch_bounds__(256, 2) k_gemm_mma(const float* __restrict__ Wm,
                                                     const float* __restrict__ bias,
                                                     const float* __restrict__ gamma,
                                                     const float* __restrict__ beta,
                                                     float* __restrict__ outp, int nrows) {
    __shared__ float sA[2][128][36];    // raw fp32 A chunks (32 k), cp.async-filled
    __shared__ float sB[2][128][36];    // raw fp32 W chunks (32 k), cp.async-filled
    __shared__ float sScale[128], sShift[128];

    const float* __restrict__ A = (MODE == 0) ? g_agg : g_h1;
    float* __restrict__ Cp      = (MODE == 0) ? g_h1  : outp;

    int tid  = threadIdx.x;
    int wid  = tid >> 5, lane = tid & 31;
    int g    = lane >> 2, t4 = lane & 3;
    int wm   = (wid >> 2) * 64;
    int wn   = (wid & 3) * 32;
    int rowbase = blockIdx.x * 128;

    if (MODE == 1 && tid < D) {
        float invN = 1.0f / (float)nrows;
        float mu   = g_sum[tid] * invN;
        float var  = g_sq[tid] * invN - mu * mu;
        float sc   = rsqrtf(var + 1e-5f) * gamma[tid];
        sScale[tid] = sc;
        sShift[tid] = beta[tid] - mu * sc;
    }

    int rS  = tid >> 3;                 // 0..31 row slot
    int c4S = tid & 7;                  // float4 column within chunk

    auto issue_chunk = [&](int kc, int buf) {
#pragma unroll
        for (int it = 0; it < 4; ++it) {
            int r = rS + it * 32;
            int grow = rowbase + r;
            uint32_t dstA = smem_u32(&sA[buf][r][c4S * 4]);
            const float* srcA = A + (size_t)grow * D + kc * 32 + c4S * 4;
            int valid = (grow < nrows) ? 16 : 0;
            asm volatile("cp.async.cg.shared.global [%0], [%1], 16, %2;"
                         :: "r"(dstA), "l"(srcA), "r"(valid) : "memory");
            uint32_t dstB = smem_u32(&sB[buf][r][c4S * 4]);
            const float* srcB = Wm + (size_t)r * D + kc * 32 + c4S * 4;
            asm volatile("cp.async.cg.shared.global [%0], [%1], 16;"
                         :: "r"(dstB), "l"(srcB) : "memory");
        }
        asm volatile("cp.async.commit_group;" ::: "memory");
    };

    float acc[4][4][4];
#pragma unroll
    for (int mi = 0; mi < 4; mi++)
#pragma unroll
        for (int nj = 0; nj < 4; nj++)
#pragma unroll
            for (int q = 0; q < 4; q++) acc[mi][nj][q] = 0.f;

    issue_chunk(0, 0);

    for (int kc = 0; kc < 4; ++kc) {
        int buf = kc & 1;
        asm volatile("cp.async.wait_group 0;" ::: "memory");
        __syncthreads();    // chunk kc visible; all warps past MMA(kc-1) reads of buf^1
        if (kc < 3) issue_chunk(kc + 1, buf ^ 1);   // overlaps MMA(kc) below

#pragma unroll
        for (int ks = 0; ks < 4; ++ks) {
            int ka = ks * 8;
            float sc0 = 0.f, sh0 = 0.f, sc1 = 0.f, sh1 = 0.f;
            if (MODE == 1) {
                int kw = kc * 32 + ka;
                sc0 = sScale[kw + t4];     sh0 = sShift[kw + t4];
                sc1 = sScale[kw + t4 + 4]; sh1 = sShift[kw + t4 + 4];
            }
            uint32_t af[4][4];
#pragma unroll
            for (int mi = 0; mi < 4; mi++) {
                int r = wm + mi * 16 + g;
                float a0 = sA[buf][r    ][ka + t4    ];
                float a1 = sA[buf][r + 8][ka + t4    ];
                float a2 = sA[buf][r    ][ka + t4 + 4];
                float a3 = sA[buf][r + 8][ka + t4 + 4];
                if (MODE == 1) {
                    a0 = fmaxf(fmaf(a0, sc0, sh0), 0.f);
                    a1 = fmaxf(fmaf(a1, sc0, sh0), 0.f);
                    a2 = fmaxf(fmaf(a2, sc1, sh1), 0.f);
                    a3 = fmaxf(fmaf(a3, sc1, sh1), 0.f);
                }
                af[mi][0] = f2tf32(a0);
                af[mi][1] = f2tf32(a1);
                af[mi][2] = f2tf32(a2);
                af[mi][3] = f2tf32(a3);
            }
            uint32_t bf[4][2];
#pragma unroll
            for (int nj = 0; nj < 4; nj++) {
                int c = wn + nj * 8 + g;
                bf[nj][0] = f2tf32(sB[buf][c][ka + t4    ]);
                bf[nj][1] = f2tf32(sB[buf][c][ka + t4 + 4]);
            }
#pragma unroll
            for (int mi = 0; mi < 4; mi++)
#pragma unroll
                for (int nj = 0; nj < 4; nj++)
                    mma_tf32(acc[mi][nj], af[mi], bf[nj]);
        }
    }

    // ---- epilogue: bias add, store, (MODE 0) fused BN column stats ----
    float bj0[4], bj1[4];
#pragma unroll
    for (int nj = 0; nj < 4; nj++) {
        int c = wn + nj * 8 + 2 * t4;
        bj0[nj] = bias[c];
        bj1[nj] = bias[c + 1];
    }

    float s0[4], s1[4], q0[4], q1[4];
#pragma unroll
    for (int nj = 0; nj < 4; nj++) { s0[nj] = s1[nj] = q0[nj] = q1[nj] = 0.f; }

#pragma unroll
    for (int mi = 0; mi < 4; mi++) {
        int r0 = rowbase + wm + mi * 16 + g;
        int r1 = r0 + 8;
#pragma unroll
        for (int nj = 0; nj < 4; nj++) {
            int c = wn + nj * 8 + 2 * t4;
            float v00 = acc[mi][nj][0] + bj0[nj];
            float v01 = acc[mi][nj][1] + bj1[nj];
            float v10 = acc[mi][nj][2] + bj0[nj];
            float v11 = acc[mi][nj][3] + bj1[nj];
            if (r0 < nrows) {
                *(float2*)&Cp[(size_t)r0 * D + c] = make_float2(v00, v01);
                if (MODE == 0) {
                    s0[nj] += v00; s1[nj] += v01;
                    q0[nj] = fmaf(v00, v00, q0[nj]); q1[nj] = fmaf(v01, v01, q1[nj]);
                }
            }
            if (r1 < nrows) {
                *(float2*)&Cp[(size_t)r1 * D + c] = make_float2(v10, v11);
                if (MODE == 0) {
                    s0[nj] += v10; s1[nj] += v11;
                    q0[nj] = fmaf(v10, v10, q0[nj]); q1[nj] = fmaf(v11, v11, q1[nj]);
                }
            }
        }
    }

    if (MODE == 0) {
#pragma unroll
        for (int nj = 0; nj < 4; nj++) {
#pragma unroll
            for (int m = 4; m <= 16; m <<= 1) {
                s0[nj] += __shfl_xor_sync(0xFFFFFFFFu, s0[nj], m);
                s1[nj] += __shfl_xor_sync(0xFFFFFFFFu, s1[nj], m);
                q0[nj] += __shfl_xor_sync(0xFFFFFFFFu, q0[nj], m);
                q1[nj] += __shfl_xor_sync(0xFFFFFFFFu, q1[nj], m);
            }
        }
        if (lane < 4) {
#pragma unroll
            for (int nj = 0; nj < 4; nj++) {
                int c = wn + nj * 8 + 2 * t4;
                atomicAdd(&g_sum[c],     s0[nj]);
                atomicAdd(&g_sum[c + 1], s1[nj]);
                atomicAdd(&g_sq [c],     q0[nj]);
                atomicAdd(&g_sq [c + 1], q1[nj]);
            }
        }
    }
}

// ---------------- launch ----------------
extern "C" void kernel_launch(void* const* d_in, const int* in_sizes, int n_in,
                              void* d_out, int out_size) {
    const float* x     = (const float*)d_in[0];
    const int*   src   = (const int*)d_in[1];
    const int*   dst   = (const int*)d_in[2];
    const float* W1    = (const float*)d_in[3];
    const float* b1    = (const float*)d_in[4];
    const float* gamma = (const float*)d_in[5];
    const float* beta  = (const float*)d_in[6];
    const float* W2    = (const float*)d_in[7];
    const float* b2    = (const float*)d_in[8];
    const float* eps   = (const float*)d_in[9];
    float* out = (float*)d_out;

    int N = in_sizes[0] / D;     // 40000
    int E = in_sizes[1];         // 640000
    int n4 = N * D4;

    k_init_agg<<<(n4 + 255) / 256, 256>>>(x, eps, n4);
    k_scatter<<<2048, 256>>>(x, src, dst, E, N);

    int gb = (N + 127) / 128;
    k_gemm_mma<0><<<gb, 256>>>(W1, b1, nullptr, nullptr, nullptr, N);  // + fused BN stats
    k_gemm_mma<1><<<gb, 256>>>(W2, b2, gamma, beta, out, N);           // BN folded in prologue
}